// round 10
// baseline (speedup 1.0000x reference)
#include <cuda_runtime.h>
#include <math_constants.h>

// ---------------------------------------------------------------------------
// MAB: ragged multi-head attention block.
//   qp = q@Wq+bq ; kp = k@Wk+bk ; vp = k@Wv+bv   (kp/vp fused: shared A operand)
//   per (batch,head): flash attention over the batch's tokens, + qp residual
//   out = ao + relu(ao@Wo + bo)
// ---------------------------------------------------------------------------

#define NMAX 16384
#define BBATCH 16

__device__ float g_qp[NMAX * 256];
__device__ float g_kp[NMAX * 256];
__device__ float g_vp[NMAX * 256];
__device__ float g_ao[NMAX * 256];
__device__ int   g_starts[BBATCH + 1];

// --------------------------- batch start offsets ---------------------------
__global__ void starts_kernel(const int* __restrict__ batch, int N) {
    int b = threadIdx.x;
    if (b > BBATCH) return;
    int lo = 0, hi = N;
    while (lo < hi) {
        int mid = (lo + hi) >> 1;
        if (batch[mid] < b) lo = mid + 1; else hi = mid;
    }
    g_starts[b] = lo;
}

// ------------------------- SGEMM (single output) ----------------------------
// 128x128 block, 8x8 micro-tile: 64 FMA per 4 LDS.128 (half the crossbar
// demand of an 8x4 shape).
// MODE 0: C = A@W + bias
// MODE 1: C = R + relu(A@W + bias)
template <int MODE>
__global__ void __launch_bounds__(256)
gemm_kernel(const float* __restrict__ A, const float* __restrict__ W,
            const float* __restrict__ bias, const float* __restrict__ R,
            float* __restrict__ C, int N) {
    const int BM = 128, BN = 128, BK = 16;
    __shared__ float As[BK][BM];   // transposed A tile
    __shared__ float Ws[BK][BN];

    int tid = threadIdx.x;
    int bm0 = blockIdx.x * BM;
    int bn0 = blockIdx.y * BN;
    int tx = tid & 15;             // 16 col groups of 8
    int ty = tid >> 4;             // 16 row groups of 8

    float acc[8][8];
#pragma unroll
    for (int i = 0; i < 8; i++)
#pragma unroll
        for (int j = 0; j < 8; j++) acc[i][j] = 0.f;

    for (int k0 = 0; k0 < 256; k0 += BK) {
        // A tile: 128 rows x 16 k = 512 float4, 2 per thread, stored transposed
#pragma unroll
        for (int i = 0; i < 2; i++) {
            int f = tid + i * 256;          // 0..511
            int row = f >> 2;               // 0..127
            int kq = f & 3;
            float4 v = make_float4(0.f, 0.f, 0.f, 0.f);
            int grow = bm0 + row;
            if (grow < N)
                v = *(const float4*)(A + (size_t)grow * 256 + k0 + kq * 4);
            As[kq * 4 + 0][row] = v.x;
            As[kq * 4 + 1][row] = v.y;
            As[kq * 4 + 2][row] = v.z;
            As[kq * 4 + 3][row] = v.w;
        }
        // W tile: 16 k rows x 128 cols = 512 float4, 2 per thread
#pragma unroll
        for (int i = 0; i < 2; i++) {
            int f = tid + i * 256;          // 0..511
            int kk = f >> 5;                // 0..15
            int cq = f & 31;                // 0..31
            float4 v = *(const float4*)(W + (size_t)(k0 + kk) * 256 + bn0 + cq * 4);
            *(float4*)&Ws[kk][cq * 4] = v;
        }
        __syncthreads();

#pragma unroll
        for (int kk = 0; kk < BK; kk++) {
            float4 w0 = *(const float4*)&Ws[kk][tx * 8];
            float4 w1 = *(const float4*)&Ws[kk][tx * 8 + 4];
            float4 a0 = *(const float4*)&As[kk][ty * 8];
            float4 a1 = *(const float4*)&As[kk][ty * 8 + 4];
            float av[8] = {a0.x, a0.y, a0.z, a0.w, a1.x, a1.y, a1.z, a1.w};
            float wv[8] = {w0.x, w0.y, w0.z, w0.w, w1.x, w1.y, w1.z, w1.w};
#pragma unroll
            for (int i = 0; i < 8; i++)
#pragma unroll
                for (int j = 0; j < 8; j++)
                    acc[i][j] += av[i] * wv[j];
        }
        __syncthreads();
    }

    float4 b0 = *(const float4*)(bias + bn0 + tx * 8);
    float4 b1 = *(const float4*)(bias + bn0 + tx * 8 + 4);
    float bvv[8] = {b0.x, b0.y, b0.z, b0.w, b1.x, b1.y, b1.z, b1.w};
#pragma unroll
    for (int i = 0; i < 8; i++) {
        int row = bm0 + ty * 8 + i;
        if (row < N) {
#pragma unroll
            for (int half = 0; half < 2; half++) {
                float4 o;
                o.x = acc[i][half * 4 + 0] + bvv[half * 4 + 0];
                o.y = acc[i][half * 4 + 1] + bvv[half * 4 + 1];
                o.z = acc[i][half * 4 + 2] + bvv[half * 4 + 2];
                o.w = acc[i][half * 4 + 3] + bvv[half * 4 + 3];
                if (MODE == 1) {
                    float4 r = *(const float4*)(R + (size_t)row * 256 + bn0 + tx * 8 + half * 4);
                    o.x = r.x + fmaxf(o.x, 0.f);
                    o.y = r.y + fmaxf(o.y, 0.f);
                    o.z = r.z + fmaxf(o.z, 0.f);
                    o.w = r.w + fmaxf(o.w, 0.f);
                }
                *(float4*)(C + (size_t)row * 256 + bn0 + tx * 8 + half * 4) = o;
            }
        }
    }
}

// ----------------------- fused dual SGEMM (shared A) ------------------------
// C = A@W + bias ; C2 = A@W2 + bias2.  128x64 block, two 8x4 acc sets.
__global__ void __launch_bounds__(256)
gemm_dual_kernel(const float* __restrict__ A,
                 const float* __restrict__ W, const float* __restrict__ bias,
                 float* __restrict__ C,
                 const float* __restrict__ W2, const float* __restrict__ bias2,
                 float* __restrict__ C2, int N) {
    const int BM = 128, BN = 64, BK = 16;
    __shared__ float As[BK][BM];
    __shared__ float Ws[BK][BN];
    __shared__ float Ws2[BK][BN];

    int tid = threadIdx.x;
    int bm0 = blockIdx.x * BM;
    int bn0 = blockIdx.y * BN;
    int tx = tid & 15;
    int ty = tid >> 4;

    float acc[8][4], acc2[8][4];
#pragma unroll
    for (int i = 0; i < 8; i++)
#pragma unroll
        for (int j = 0; j < 4; j++) { acc[i][j] = 0.f; acc2[i][j] = 0.f; }

    for (int k0 = 0; k0 < 256; k0 += BK) {
#pragma unroll
        for (int i = 0; i < 2; i++) {
            int f = tid + i * 256;
            int row = f >> 2;
            int kq = f & 3;
            float4 v = make_float4(0.f, 0.f, 0.f, 0.f);
            int grow = bm0 + row;
            if (grow < N)
                v = *(const float4*)(A + (size_t)grow * 256 + k0 + kq * 4);
            As[kq * 4 + 0][row] = v.x;
            As[kq * 4 + 1][row] = v.y;
            As[kq * 4 + 2][row] = v.z;
            As[kq * 4 + 3][row] = v.w;
        }
        {
            int kk = tid >> 4;
            int cq = tid & 15;
            float4 v = *(const float4*)(W + (size_t)(k0 + kk) * 256 + bn0 + cq * 4);
            *(float4*)&Ws[kk][cq * 4] = v;
            float4 v2 = *(const float4*)(W2 + (size_t)(k0 + kk) * 256 + bn0 + cq * 4);
            *(float4*)&Ws2[kk][cq * 4] = v2;
        }
        __syncthreads();

#pragma unroll
        for (int kk = 0; kk < BK; kk++) {
            float4 w  = *(const float4*)&Ws[kk][tx * 4];
            float4 w2 = *(const float4*)&Ws2[kk][tx * 4];
            float4 a0 = *(const float4*)&As[kk][ty * 8];
            float4 a1 = *(const float4*)&As[kk][ty * 8 + 4];
            float av[8] = {a0.x, a0.y, a0.z, a0.w, a1.x, a1.y, a1.z, a1.w};
#pragma unroll
            for (int i = 0; i < 8; i++) {
                acc[i][0]  += av[i] * w.x;
                acc[i][1]  += av[i] * w.y;
                acc[i][2]  += av[i] * w.z;
                acc[i][3]  += av[i] * w.w;
                acc2[i][0] += av[i] * w2.x;
                acc2[i][1] += av[i] * w2.y;
                acc2[i][2] += av[i] * w2.z;
                acc2[i][3] += av[i] * w2.w;
            }
        }
        __syncthreads();
    }

    float4 bv4  = *(const float4*)(bias  + bn0 + tx * 4);
    float4 bv4b = *(const float4*)(bias2 + bn0 + tx * 4);
#pragma unroll
    for (int i = 0; i < 8; i++) {
        int row = bm0 + ty * 8 + i;
        if (row < N) {
            float4 o;
            o.x = acc[i][0] + bv4.x;
            o.y = acc[i][1] + bv4.y;
            o.z = acc[i][2] + bv4.z;
            o.w = acc[i][3] + bv4.w;
            *(float4*)(C + (size_t)row * 256 + bn0 + tx * 4) = o;
            float4 o2;
            o2.x = acc2[i][0] + bv4b.x;
            o2.y = acc2[i][1] + bv4b.y;
            o2.z = acc2[i][2] + bv4b.z;
            o2.w = acc2[i][3] + bv4b.w;
            *(float4*)(C2 + (size_t)row * 256 + bn0 + tx * 4) = o2;
        }
    }
}

// ---------------------------- flash attention -------------------------------
// grid: (qtiles, H, B); block: 128 threads, TWO queries per thread
// (q0 = base+tid, q1 = base+tid+128): each broadcast K/V float from SMEM feeds
// 2 FMAs, halving the L1 crossbar demand ncu showed as the bottleneck
// (L1=70.5% vs fma=37.7%).
// K/V tiles are DOUBLE-BUFFERED (one __syncthreads per tile, LDG latency
// overlapped with compute). Online softmax in 8-key chunks; the O/l rescale
// is SKIPPED when the running max is unchanged (bit-exact); the 1/sqrt(DH)
// scale is folded into the Q registers once at load (removes the per-score
// multiply from the QK critical path).
__global__ void __launch_bounds__(128)
attn_kernel(const float* __restrict__ qp, const float* __restrict__ kp,
            const float* __restrict__ vp, float* __restrict__ ao) {
    const int KT = 32;
    __shared__ float Ks[2][KT][32];
    __shared__ float Vs[2][KT][32];

    int b = blockIdx.z;
    int h = blockIdx.y;
    int s0 = g_starts[b];
    int L  = g_starts[b + 1] - s0;
    if ((int)(blockIdx.x * 256) >= L) return;

    int q0 = blockIdx.x * 256 + threadIdx.x;
    int q1 = q0 + 128;
    bool a0 = (q0 < L);
    bool a1 = (q1 < L);
    int r0 = s0 + (a0 ? q0 : 0);
    int r1 = s0 + (a1 ? q1 : 0);

    const float scale = 0.17677669529663687f;  // 1/sqrt(32)
    float Q0[32], Q1[32];
    {
        const float* qr0 = qp + (size_t)r0 * 256 + (h << 5);
        const float* qr1 = qp + (size_t)r1 * 256 + (h << 5);
#pragma unroll
        for (int dq = 0; dq < 8; dq++) {
            float4 v = ((const float4*)qr0)[dq];
            Q0[dq * 4 + 0] = v.x * scale; Q0[dq * 4 + 1] = v.y * scale;
            Q0[dq * 4 + 2] = v.z * scale; Q0[dq * 4 + 3] = v.w * scale;
            float4 u = ((const float4*)qr1)[dq];
            Q1[dq * 4 + 0] = u.x * scale; Q1[dq * 4 + 1] = u.y * scale;
            Q1[dq * 4 + 2] = u.z * scale; Q1[dq * 4 + 3] = u.w * scale;
        }
    }

    float m0 = -1e30f, l0 = 0.f;
    float m1 = -1e30f, l1 = 0.f;
    float O0[32], O1[32];
#pragma unroll
    for (int d = 0; d < 32; d++) { O0[d] = 0.f; O1[d] = 0.f; }

    // two cooperative-load slots per thread (256 float4 per tensor per tile)
    int f0 = threadIdx.x;            // slot 0
    int f1 = threadIdx.x + 128;      // slot 1
    int j0 = f0 >> 3, d0 = f0 & 7;
    int j1 = f1 >> 3, d1 = f1 & 7;

    int nt = (L + KT - 1) / KT;
    float4 pk0, pk1, pv0, pv1;       // prefetch registers

    // prologue: fetch tile 0 and stage into buffer 0
    {
        int kr0 = j0, kr1 = j1;      // kbase = 0
        pk0 = pk1 = pv0 = pv1 = make_float4(0.f, 0.f, 0.f, 0.f);
        if (kr0 < L) {
            pk0 = ((const float4*)(kp + (size_t)(s0 + kr0) * 256 + (h << 5)))[d0];
            pv0 = ((const float4*)(vp + (size_t)(s0 + kr0) * 256 + (h << 5)))[d0];
        }
        if (kr1 < L) {
            pk1 = ((const float4*)(kp + (size_t)(s0 + kr1) * 256 + (h << 5)))[d1];
            pv1 = ((const float4*)(vp + (size_t)(s0 + kr1) * 256 + (h << 5)))[d1];
        }
        *(float4*)&Ks[0][j0][d0 * 4] = pk0;
        *(float4*)&Vs[0][j0][d0 * 4] = pv0;
        *(float4*)&Ks[0][j1][d1 * 4] = pk1;
        *(float4*)&Vs[0][j1][d1 * 4] = pv1;
    }
    __syncthreads();

    for (int kt = 0; kt < nt; kt++) {
        int buf = kt & 1;
        int kbase = kt * KT;
        bool more = (kt + 1 < nt);

        // issue next tile's global loads (latency overlapped with compute)
        if (more) {
            int nb = kbase + KT;
            int kr0 = nb + j0, kr1 = nb + j1;
            pk0 = pk1 = pv0 = pv1 = make_float4(0.f, 0.f, 0.f, 0.f);
            if (kr0 < L) {
                pk0 = ((const float4*)(kp + (size_t)(s0 + kr0) * 256 + (h << 5)))[d0];
                pv0 = ((const float4*)(vp + (size_t)(s0 + kr0) * 256 + (h << 5)))[d0];
            }
            if (kr1 < L) {
                pk1 = ((const float4*)(kp + (size_t)(s0 + kr1) * 256 + (h << 5)))[d1];
                pv1 = ((const float4*)(vp + (size_t)(s0 + kr1) * 256 + (h << 5)))[d1];
            }
        }

#pragma unroll 1
        for (int c = 0; c < 4; c++) {
            int cb = kbase + c * 8;
            float s0a[8], s1a[8];
            float tmax0 = -1e30f, tmax1 = -1e30f;
#pragma unroll
            for (int j = 0; j < 8; j++) {
                float acc0 = 0.f, acc1 = 0.f;
#pragma unroll
                for (int dq = 0; dq < 8; dq++) {
                    float4 k4 = *(const float4*)&Ks[buf][c * 8 + j][dq * 4];
                    acc0 += Q0[dq * 4 + 0] * k4.x;
                    acc0 += Q0[dq * 4 + 1] * k4.y;
                    acc0 += Q0[dq * 4 + 2] * k4.z;
                    acc0 += Q0[dq * 4 + 3] * k4.w;
                    acc1 += Q1[dq * 4 + 0] * k4.x;
                    acc1 += Q1[dq * 4 + 1] * k4.y;
                    acc1 += Q1[dq * 4 + 2] * k4.z;
                    acc1 += Q1[dq * 4 + 3] * k4.w;
                }
                bool inb = (cb + j < L);
                s0a[j] = inb ? acc0 : -1e30f;
                s1a[j] = inb ? acc1 : -1e30f;
                tmax0 = fmaxf(tmax0, s0a[j]);
                tmax1 = fmaxf(tmax1, s1a[j]);
            }
            // rescale only when the running max actually changed (bit-exact:
            // the skipped path would multiply l and O by exp(0) = 1).
            if (tmax0 > m0) {
                float c0 = __expf(m0 - tmax0);
                l0 *= c0;
#pragma unroll
                for (int d = 0; d < 32; d++) O0[d] *= c0;
                m0 = tmax0;
            }
            if (tmax1 > m1) {
                float c1 = __expf(m1 - tmax1);
                l1 *= c1;
#pragma unroll
                for (int d = 0; d < 32; d++) O1[d] *= c1;
                m1 = tmax1;
            }
#pragma unroll
            for (int j = 0; j < 8; j++) {
                float p0 = __expf(s0a[j] - m0);
                float p1 = __expf(s1a[j] - m1);
                l0 += p0; l1 += p1;
#pragma unroll
                for (int dq = 0; dq < 8; dq++) {
                    float4 v4 = *(const float4*)&Vs[buf][c * 8 + j][dq * 4];
                    O0[dq * 4 + 0] += p0 * v4.x;
                    O0[dq * 4 + 1] += p0 * v4.y;
                    O0[dq * 4 + 2] += p0 * v4.z;
                    O0[dq * 4 + 3] += p0 * v4.w;
                    O1[dq * 4 + 0] += p1 * v4.x;
                    O1[dq * 4 + 1] += p1 * v4.y;
                    O1[dq * 4 + 2] += p1 * v4.z;
                    O1[dq * 4 + 3] += p1 * v4.w;
                }
            }
        }

        // stage the prefetched tile into the other buffer; the sync at the
        // end of the PREVIOUS iteration guarantees nobody still reads it.
        if (more) {
            int nb2 = buf ^ 1;
            *(float4*)&Ks[nb2][j0][d0 * 4] = pk0;
            *(float4*)&Vs[nb2][j0][d0 * 4] = pv0;
            *(float4*)&Ks[nb2][j1][d1 * 4] = pk1;
            *(float4*)&Vs[nb2][j1][d1 * 4] = pv1;
            __syncthreads();
        }
    }

    if (a0) {
        float inv = 1.f / l0;
        const float* qr = qp + (size_t)r0 * 256 + (h << 5);
        float* orow = ao + (size_t)r0 * 256 + (h << 5);
#pragma unroll
        for (int dq = 0; dq < 8; dq++) {
            float4 qv = ((const float4*)qr)[dq];
            float4 ov;
            ov.x = O0[dq * 4 + 0] * inv + qv.x;
            ov.y = O0[dq * 4 + 1] * inv + qv.y;
            ov.z = O0[dq * 4 + 2] * inv + qv.z;
            ov.w = O0[dq * 4 + 3] * inv + qv.w;
            ((float4*)orow)[dq] = ov;
        }
    }
    if (a1) {
        float inv = 1.f / l1;
        const float* qr = qp + (size_t)r1 * 256 + (h << 5);
        float* orow = ao + (size_t)r1 * 256 + (h << 5);
#pragma unroll
        for (int dq = 0; dq < 8; dq++) {
            float4 qv = ((const float4*)qr)[dq];
            float4 ov;
            ov.x = O1[dq * 4 + 0] * inv + qv.x;
            ov.y = O1[dq * 4 + 1] * inv + qv.y;
            ov.z = O1[dq * 4 + 2] * inv + qv.z;
            ov.w = O1[dq * 4 + 3] * inv + qv.w;
            ((float4*)orow)[dq] = ov;
        }
    }
}

// ------------------------------ launcher ------------------------------------
extern "C" void kernel_launch(void* const* d_in, const int* in_sizes, int n_in,
                              void* d_out, int out_size) {
    const float* q       = (const float*)d_in[0];
    const float* k       = (const float*)d_in[1];
    const int*   batch_q = (const int*)d_in[2];
    // d_in[3] = batch_k (identical to batch_q)
    const float* Wq = (const float*)d_in[4];
    const float* bq = (const float*)d_in[5];
    const float* Wk = (const float*)d_in[6];
    const float* bk = (const float*)d_in[7];
    const float* Wv = (const float*)d_in[8];
    const float* bv = (const float*)d_in[9];
    const float* Wo = (const float*)d_in[10];
    const float* bo = (const float*)d_in[11];
    float* out = (float*)d_out;

    int N = in_sizes[0] / 256;

    void *p_qp, *p_kp, *p_vp, *p_ao;
    cudaGetSymbolAddress(&p_qp, g_qp);
    cudaGetSymbolAddress(&p_kp, g_kp);
    cudaGetSymbolAddress(&p_vp, g_vp);
    cudaGetSymbolAddress(&p_ao, g_ao);
    float* qp = (float*)p_qp;
    float* kp = (float*)p_kp;
    float* vp = (float*)p_vp;
    float* ao = (float*)p_ao;

    starts_kernel<<<1, 32>>>(batch_q, N);

    dim3 gg1((N + 127) / 128, 2);   // 128x128 blocks
    dim3 gg2((N + 127) / 128, 4);   // 128x64 blocks (dual)

    // qp = q@Wq + bq
    gemm_kernel<0><<<gg1, 256>>>(q, Wq, bq, nullptr, qp, N);
    // kp = k@Wk + bk ; vp = k@Wv + bv  (fused: k's A-tiles loaded once)
    gemm_dual_kernel<<<gg2, 256>>>(k, Wk, bk, kp, Wv, bv, vp, N);

    dim3 ga(4 /* ceil(1024/256) */, 8 /* H */, BBATCH);
    attn_kernel<<<ga, 128>>>(qp, kp, vp, ao);

    // out = ao + relu(ao@Wo + bo)
    gemm_kernel<1><<<gg1, 256>>>(ao, Wo, bo, ao, out, N);
}